// round 11
// baseline (speedup 1.0000x reference)
#include <cuda_runtime.h>
#include <cuda_bf16.h>
#include <cstdint>
#include <math.h>

#define BATCH 8
#define DM    256
#define TLEN  2048
#define TP    (TLEN/2)
#define DIN   514
#define GDEC  576
#define NL    4
#define NST   32
#define KPE   576
#define KTE   (6*KPE)   // 3456

typedef unsigned long long u64;

// ---------------- scratch ----------------
__device__ __align__(16) float g_zr [BATCH*DM*TLEN];
__device__ __align__(16) float g_zi [BATCH*DM*TLEN];
__device__ __align__(16) float g_ygr[BATCH*DM*TLEN];
__device__ __align__(16) float g_ygi[BATCH*DM*TLEN];
__device__ __align__(16) float g_or [BATCH*DM*TLEN];
__device__ __align__(16) float g_oi [BATCH*DM*TLEN];
__device__ float g_ar [NL*DM*NST];
__device__ float g_ai [NL*DM*NST];
__device__ float g_cr [NL*DM*NST];
__device__ float g_ci [NL*DM*NST];
// FFMA-path prepacked weights (outlin/decoder), [k][g] layout, u64 broadcasts
__device__ __align__(16) u64 g_woRR[NL*DM*DM], g_woPI[NL*DM*DM], g_woNI[NL*DM*DM];
__device__ __align__(16) u64 g_wdRR[DM*GDEC], g_wdPI[DM*GDEC], g_wdNI[DM*GDEC];
// MMA encoder operands
__device__ __align__(16) __nv_bfloat16 g_xe[(long)BATCH*TLEN*KTE];   // [b][t][K']
__device__ __align__(16) __nv_bfloat16 g_aenc[512*KTE];              // [m][K']

// ---------------- helpers -------------------------------------------------------
__device__ __forceinline__ u64 pk(float lo, float hi) {
    u64 r; asm("mov.b64 %0, {%1, %2};" : "=l"(r) : "f"(lo), "f"(hi)); return r;
}
__device__ __forceinline__ float2 upk(u64 v) {
    float2 f; asm("mov.b64 {%0, %1}, %2;" : "=f"(f.x), "=f"(f.y) : "l"(v)); return f;
}
__device__ __forceinline__ void fma2(u64& acc, u64 a, u64 b) {
    asm("fma.rn.f32x2 %0, %1, %2, %0;" : "+l"(acc) : "l"(a), "l"(b));
}
__device__ __forceinline__ void cp16(u64* smem_dst, const u64* gsrc) {
    unsigned sa = (unsigned)__cvta_generic_to_shared(smem_dst);
    asm volatile("cp.async.cg.shared.global [%0], [%1], 16;" :: "r"(sa), "l"(gsrc));
}
__device__ __forceinline__ void mma16816(float* c, const uint32_t* a, uint32_t b0, uint32_t b1) {
    asm volatile("mma.sync.aligned.m16n8k16.row.col.f32.bf16.bf16.f32 "
                 "{%0,%1,%2,%3}, {%4,%5,%6,%7}, {%8,%9}, {%0,%1,%2,%3};"
                 : "+f"(c[0]), "+f"(c[1]), "+f"(c[2]), "+f"(c[3])
                 : "r"(a[0]), "r"(a[1]), "r"(a[2]), "r"(a[3]), "r"(b0), "r"(b1));
}
__device__ __forceinline__ float gelu_tanh(float x) {
    float x3 = x * x * x;
    float t  = 0.7978845608028654f * fmaf(0.044715f, x3, x);
    float th;
    asm("tanh.approx.f32 %0, %1;" : "=f"(th) : "f"(t));
    return 0.5f * x * (1.0f + th);
}

// ---------------- S4D coefficient precompute ------------------------------------
__global__ void precompute_kernel(const float* __restrict__ log_dt,
                                  const float* __restrict__ log_A_real,
                                  const float* __restrict__ A_imag,
                                  const float* __restrict__ C_r,
                                  const float* __restrict__ C_i)
{
    int idx = blockIdx.x * blockDim.x + threadIdx.x;
    if (idx >= NL*DM*NST) return;
    int h = (idx / NST) % DM;
    int l = idx / (NST*DM);
    double dt  = exp((double)log_dt[l*DM + h]);
    double Are = -exp((double)log_A_real[idx]);
    double Aim = (double)A_imag[idx];
    double er  = exp(Are * dt);
    double arr = er * cos(Aim * dt);
    double aii = er * sin(Aim * dt);
    g_ar[idx] = (float)arr;
    g_ai[idx] = (float)aii;
    double e1r = arr - 1.0, e1i = aii;
    double den = Are*Are + Aim*Aim;
    double qr  = (e1r*Are + e1i*Aim) / den;
    double qi  = (e1i*Are - e1r*Aim) / den;
    double cr  = (double)C_r[idx], ci = (double)C_i[idx];
    g_cr[idx] = (float)(cr*qr - ci*qi);
    g_ci[idx] = (float)(cr*qi + ci*qr);
}

// ---------------- FFMA weight prepack (outlin/decoder) ---------------------------
__global__ void pack_out(const float* __restrict__ Wr, const float* __restrict__ Wi)
{
    int idx = blockIdx.x * blockDim.x + threadIdx.x;
    if (idx >= NL*DM*DM) return;
    int g = idx % DM;
    int k = (idx / DM) % DM;
    int l = idx / (DM*DM);
    float wr = Wr[((long)l*DM + g)*DM + k];
    float wi = Wi[((long)l*DM + g)*DM + k];
    g_woRR[idx] = pk(wr, wr);
    g_woPI[idx] = pk(wi, wi);
    g_woNI[idx] = pk(-wi, -wi);
}
__global__ void pack_dec(const float* __restrict__ Wr, const float* __restrict__ Wi)
{
    int idx = blockIdx.x * blockDim.x + threadIdx.x;
    if (idx >= DM*GDEC) return;
    int g = idx % GDEC, k = idx / GDEC;
    float wr = 0.f, wi = 0.f;
    if (g < DIN) { wr = Wr[(long)g*DM + k]; wi = Wi[(long)g*DM + k]; }
    g_wdRR[idx] = pk(wr, wr);
    g_wdPI[idx] = pk(wi, wi);
    g_wdNI[idx] = pk(-wi, -wi);
}

// ---------------- MMA encoder prepack -------------------------------------------
// Row m<256 (R, g=m):   [WrH, WrH, WrL, -WiH, -WiH, -WiL]
// Row m>=256 (I, g=m-256): [WiH, WiH, WiL,  WrH,  WrH,  WrL]
__global__ void packA_enc(const float* __restrict__ Wr, const float* __restrict__ Wi)
{
    long idx = (long)blockIdx.x*blockDim.x + threadIdx.x;
    if (idx >= (long)512*KTE) return;
    int m  = (int)(idx / KTE);
    int kp = (int)(idx % KTE);
    int bk = kp / KPE, k = kp % KPE;
    int isR = m < 256;
    int g = isR ? m : m - 256;
    float w = 0.f;
    if (k < DIN) {
        const float* W = isR ? (bk < 3 ? Wr : Wi) : (bk < 3 ? Wi : Wr);
        float s = (isR && bk >= 3) ? -1.f : 1.f;
        w = s * W[(long)g*DIN + k];
    }
    __nv_bfloat16 h = __float2bfloat16(w);
    if (bk % 3 == 2) h = __float2bfloat16(w - __bfloat162float(h));
    g_aenc[idx] = h;
}

// ---------------- encoder X convert: transpose + hi/lo split ---------------------
// B blocks: [XrH, XrL, XrH, XiH, XiL, XiH]; g_xe[b][t][K']
__global__ __launch_bounds__(128) void conv_xe(const float* __restrict__ xsrc)
{
    __shared__ float sre[64][65], sim[64][65];
    int tt = blockIdx.x, chunk = blockIdx.y, b = blockIdx.z;
    int tid = threadIdx.x;
    for (int idx = tid; idx < 4096; idx += 128) {
        int k = idx >> 6, t = idx & 63;
        int kg = chunk*64 + k, tg = tt*64 + t;
        float re = 0.f, im = 0.f;
        if (kg < DIN) {
            const float* p = xsrc + ((((long)b*DIN + kg)*TLEN + tg) << 1);
            re = p[0]; im = p[1];
        }
        sre[k][t] = re; sim[k][t] = im;
    }
    __syncthreads();
    for (int idx = tid; idx < 2048; idx += 128) {
        int t = idx >> 5, k2 = (idx & 31)*2;
        float r0 = sre[k2][t],   i0 = sim[k2][t];
        float r1 = sre[k2+1][t], i1 = sim[k2+1][t];
        __nv_bfloat16 rh0 = __float2bfloat16(r0), rh1 = __float2bfloat16(r1);
        __nv_bfloat16 rl0 = __float2bfloat16(r0 - __bfloat162float(rh0));
        __nv_bfloat16 rl1 = __float2bfloat16(r1 - __bfloat162float(rh1));
        __nv_bfloat16 ih0 = __float2bfloat16(i0), ih1 = __float2bfloat16(i1);
        __nv_bfloat16 il0 = __float2bfloat16(i0 - __bfloat162float(ih0));
        __nv_bfloat16 il1 = __float2bfloat16(i1 - __bfloat162float(ih1));
        uint32_t RH = ((uint32_t)*(uint16_t*)&rh1 << 16) | *(uint16_t*)&rh0;
        uint32_t RL = ((uint32_t)*(uint16_t*)&rl1 << 16) | *(uint16_t*)&rl0;
        uint32_t IH = ((uint32_t)*(uint16_t*)&ih1 << 16) | *(uint16_t*)&ih0;
        uint32_t IL = ((uint32_t)*(uint16_t*)&il1 << 16) | *(uint16_t*)&il0;
        long base = ((long)b*TLEN + tt*64 + t)*KTE + chunk*64 + k2;
        *(uint32_t*)(g_xe + base)          = RH;
        *(uint32_t*)(g_xe + base + KPE)    = RL;
        *(uint32_t*)(g_xe + base + 2*KPE)  = RH;
        *(uint32_t*)(g_xe + base + 3*KPE)  = IH;
        *(uint32_t*)(g_xe + base + 4*KPE)  = IL;
        *(uint32_t*)(g_xe + base + 5*KPE)  = IH;
    }
}

// ---------------- encoder MMA GEMM (maximum simplicity) --------------------------
// C[512][2048] = A[512][KTE] * Xe^T per b. CTA tile 128m x 64n, BK=32.
// No cp.async, no ldmatrix, no swizzle; padded smem; fragments via plain 32-bit LDS
// using the documented m16n8k16 thread maps.
__global__ __launch_bounds__(256) void mma_enc(
    const float* __restrict__ bR, const float* __restrict__ bI)
{
    __shared__ __nv_bfloat16 sA[128][40];
    __shared__ __nv_bfloat16 sB[64][40];
    int tid = threadIdx.x;
    int t0 = blockIdx.x*64, m0 = blockIdx.y*128, b = blockIdx.z;
    const __nv_bfloat16* Xb = g_xe + (long)b*TLEN*KTE;
    int wid = tid >> 5, lane = tid & 31;
    int wg = (wid >> 2)*64, wt = (wid & 3)*16;
    int gid = lane >> 2, tig = lane & 3;

    float acc[4][2][4];
#pragma unroll
    for (int i = 0; i < 4; i++)
#pragma unroll
        for (int j = 0; j < 2; j++)
#pragma unroll
            for (int r = 0; r < 4; r++) acc[i][j][r] = 0.f;

    for (int c = 0; c < KTE/32; c++) {
        // load A tile 128x32, B tile 64x32 (plain, coalesced pairs)
        for (int e = tid; e < 2048; e += 256) {
            int row = e >> 4, col = (e & 15)*2;
            *(uint32_t*)&sA[row][col] =
                *(const uint32_t*)&g_aenc[(long)(m0+row)*KTE + c*32 + col];
        }
        for (int e = tid; e < 1024; e += 256) {
            int row = e >> 4, col = (e & 15)*2;
            *(uint32_t*)&sB[row][col] =
                *(const uint32_t*)&Xb[(long)(t0+row)*KTE + c*32 + col];
        }
        __syncthreads();
#pragma unroll
        for (int kk = 0; kk < 2; kk++) {
            int cb = kk*16 + tig*2;
            uint32_t af[4][4];
#pragma unroll
            for (int mt = 0; mt < 4; mt++) {
                int r = wg + mt*16 + gid;
                af[mt][0] = *(uint32_t*)&sA[r][cb];
                af[mt][1] = *(uint32_t*)&sA[r+8][cb];
                af[mt][2] = *(uint32_t*)&sA[r][cb+8];
                af[mt][3] = *(uint32_t*)&sA[r+8][cb+8];
            }
            uint32_t bf[2][2];
#pragma unroll
            for (int nt = 0; nt < 2; nt++) {
                int n = wt + nt*8 + gid;
                bf[nt][0] = *(uint32_t*)&sB[n][cb];        // {B[k][n], B[k+1][n]}
                bf[nt][1] = *(uint32_t*)&sB[n][cb+8];
            }
#pragma unroll
            for (int mt = 0; mt < 4; mt++)
#pragma unroll
                for (int nt = 0; nt < 2; nt++)
                    mma16816(acc[mt][nt], af[mt], bf[nt][0], bf[nt][1]);
        }
        __syncthreads();
    }

#pragma unroll
    for (int mt = 0; mt < 4; mt++) {
#pragma unroll
        for (int nt = 0; nt < 2; nt++) {
            int t = t0 + wt + nt*8 + tig*2;
#pragma unroll
            for (int h = 0; h < 2; h++) {
                int mm = m0 + wg + mt*16 + gid + h*8;
                float v0 = acc[mt][nt][h*2], v1 = acc[mt][nt][h*2+1];
                int isR = mm < 256;
                int g = isR ? mm : mm - 256;
                float bb = isR ? bR[g] : bI[g];
                float* base = isR ? g_zr : g_zi;
                *(float2*)&base[((long)b*DM + g)*TLEN + t] = make_float2(v0 + bb, v1 + bb);
            }
        }
    }
}

// ---------------- FFMA pipelined complex GEMM core (proven R4) -------------------
#define STAGE_U64 2560
__device__ __forceinline__ void cgemm_pipe(u64* sm,
    const u64* __restrict__ xr, const u64* __restrict__ xi,
    const u64* __restrict__ w0, const u64* __restrict__ w1,
    const u64* __restrict__ w2,
    int Gs, int nt, u64 accR[4][4], u64 accI[4][4], int tid)
{
    int tx = tid & 15, ty = tid >> 4;
    int row = tid >> 5, c = (tid & 31) * 2;
    long xoff = (long)row * TP + c;
    long woff = (long)row * Gs + c;
    int sof = row*64 + c;
    {
        u64* d = sm;
        cp16(d + sof,        xr + xoff);
        cp16(d + 512 + sof,  xi + xoff);
        cp16(d + 1024 + sof, w0 + woff);
        cp16(d + 1536 + sof, w1 + woff);
        cp16(d + 2048 + sof, w2 + woff);
        asm volatile("cp.async.commit_group;");
    }
    for (int s = 0; s < nt; s++) {
        __syncthreads();
        if (s + 1 < nt) {
            u64* d = sm + ((s+1)&1)*STAGE_U64;
            long xo = xoff + (long)(s+1)*8*TP;
            long wo = woff + (long)(s+1)*8*Gs;
            cp16(d + sof,        xr + xo);
            cp16(d + 512 + sof,  xi + xo);
            cp16(d + 1024 + sof, w0 + wo);
            cp16(d + 1536 + sof, w1 + wo);
            cp16(d + 2048 + sof, w2 + wo);
            asm volatile("cp.async.commit_group;");
            asm volatile("cp.async.wait_group 1;");
        } else {
            asm volatile("cp.async.wait_group 0;");
        }
        __syncthreads();
        const u64* bb = sm + (s&1)*STAGE_U64;
        const u64* bX = bb;
        const u64* bY = bb + 512;
        const u64* bW0 = bb + 1024;
        const u64* bW1 = bb + 1536;
        const u64* bW2 = bb + 2048;
#pragma unroll
        for (int kk = 0; kk < 8; kk++) {
            u64 xrv[4], xiv[4];
#pragma unroll
            for (int i = 0; i < 4; i++) {
                xrv[i] = bX[kk*64 + tx + 16*i];
                xiv[i] = bY[kk*64 + tx + 16*i];
            }
#pragma unroll
            for (int j = 0; j < 4; j++) {
                u64 wrr = bW0[kk*64 + ty + 16*j];
                u64 wpi = bW1[kk*64 + ty + 16*j];
                u64 wni = bW2[kk*64 + ty + 16*j];
#pragma unroll
                for (int i = 0; i < 4; i++) {
                    fma2(accR[j][i], wrr, xrv[i]);
                    fma2(accR[j][i], wni, xiv[i]);
                    fma2(accI[j][i], wrr, xiv[i]);
                    fma2(accI[j][i], wpi, xrv[i]);
                }
            }
        }
    }
}

// ---------------- per-layer pointwise complex GEMM (DM -> DM) ---------------------
__global__ __launch_bounds__(256, 2) void outlin_gemm(int l,
    const float* __restrict__ br, const float* __restrict__ bi)
{
    __shared__ u64 sm[2*STAGE_U64];
    int b  = blockIdx.z;
    int tp0 = blockIdx.x * 64;
    int g0 = blockIdx.y * 64;
    int tid = threadIdx.x;
    int tx = tid & 15, ty = tid >> 4;
    u64 accR[4][4], accI[4][4];
#pragma unroll
    for (int j = 0; j < 4; j++)
#pragma unroll
        for (int i = 0; i < 4; i++) { accR[j][i] = 0ull; accI[j][i] = 0ull; }

    const u64* xr = reinterpret_cast<const u64*>(g_ygr) + (long)b*DM*TP + tp0;
    const u64* xi = reinterpret_cast<const u64*>(g_ygi) + (long)b*DM*TP + tp0;
    long wb = (long)l*DM*DM + g0;
    cgemm_pipe(sm, xr, xi, g_woRR + wb, g_woPI + wb, g_woNI + wb,
               DM, DM/8, accR, accI, tid);

#pragma unroll
    for (int j = 0; j < 4; j++) {
        int g = g0 + ty + 16*j;
        float bR = br[l*DM + g], bI = bi[l*DM + g];
#pragma unroll
        for (int i = 0; i < 4; i++) {
            int t = 2*(tp0 + tx + 16*i);
            long off = ((long)b*DM + g)*TLEN + t;
            float2 fR = upk(accR[j][i]);
            float2 fI = upk(accI[j][i]);
            *reinterpret_cast<float2*>(g_or + off) = make_float2(fR.x + bR, fR.y + bR);
            *reinterpret_cast<float2*>(g_oi + off) = make_float2(fI.x + bI, fI.y + bI);
        }
    }
}

// ---------------- decoder -------------------------------------------------------
__global__ __launch_bounds__(256, 2) void decoder_gemm(
    const float* __restrict__ br, const float* __restrict__ bi,
    float4* __restrict__ out)
{
    __shared__ u64 sm[2*STAGE_U64];
    int b  = blockIdx.z;
    int tp0 = blockIdx.x * 64;
    int g0 = blockIdx.y * 64;
    int tid = threadIdx.x;
    int tx = tid & 15, ty = tid >> 4;
    u64 accR[4][4], accI[4][4];
#pragma unroll
    for (int j = 0; j < 4; j++)
#pragma unroll
        for (int i = 0; i < 4; i++) { accR[j][i] = 0ull; accI[j][i] = 0ull; }

    const u64* xr = reinterpret_cast<const u64*>(g_zr) + (long)b*DM*TP + tp0;
    const u64* xi = reinterpret_cast<const u64*>(g_zi) + (long)b*DM*TP + tp0;
    cgemm_pipe(sm, xr, xi, g_wdRR + g0, g_wdPI + g0, g_wdNI + g0,
               GDEC, DM/8, accR, accI, tid);

#pragma unroll
    for (int j = 0; j < 4; j++) {
        int g = g0 + ty + 16*j;
        if (g >= DIN) continue;
        float bR = br[g], bI = bi[g];
#pragma unroll
        for (int i = 0; i < 4; i++) {
            int t = 2*(tp0 + tx + 16*i);
            float2 fR = upk(accR[j][i]);
            float2 fI = upk(accI[j][i]);
            out[(((long)b*DIN + g)*TLEN + t) >> 1] =
                make_float4(fR.x + bR, fI.x + bI, fR.y + bR, fI.y + bI);
        }
    }
}

// ---------------- per-layer S4D scan + D-skip + gelu (warp = one (b,h)) ----------
__global__ __launch_bounds__(128) void scan_kernel(int layer, const float* __restrict__ Dvec)
{
    __shared__ float2 uS[4][32];
    __shared__ float2 prodS[4][32][34];
    int wid  = threadIdx.x >> 5;
    int lane = threadIdx.x & 31;
    int ch = blockIdx.x * 4 + wid;
    int b  = ch >> 8;
    int h  = ch & 255;
    int pidx = (layer*DM + h)*NST + lane;
    float ar = g_ar[pidx], ai = g_ai[pidx];
    float cr = g_cr[pidx], ci = g_ci[pidx];
    float Dh = Dvec[layer*DM + h];
    long base = ((long)b*DM + h)*TLEN;
    const float* zr = g_zr + base;
    const float* zi = g_zi + base;
    float* yro = g_ygr + base;
    float* yio = g_ygi + base;

    float sr = 0.f, si = 0.f;
    for (int t0 = 0; t0 < TLEN; t0 += 32) {
        float ur_l = zr[t0 + lane];
        float ui_l = zi[t0 + lane];
        uS[wid][lane] = make_float2(ur_l, ui_l);
        __syncwarp();
#pragma unroll
        for (int j = 0; j < 32; j++) {
            float2 u = uS[wid][j];
            float nsr = fmaf(ar, sr, u.x); nsr = fmaf(-ai, si, nsr);
            float nsi = fmaf(ar, si, u.y); nsi = fmaf( ai, sr, nsi);
            sr = nsr; si = nsi;
            float pr = cr * sr; pr = fmaf(-ci, si, pr);
            float pi = cr * si; pi = fmaf( ci, sr, pi);
            prodS[wid][j][lane] = make_float2(pr, pi);
        }
        __syncwarp();
        float yr = 0.f, yi = 0.f;
#pragma unroll
        for (int q = 0; q < 32; q++) {
            float2 v = prodS[wid][lane][q];
            yr += v.x; yi += v.y;
        }
        yr = fmaf(Dh, ur_l, yr);
        yi = fmaf(Dh, ui_l, yi);
        yro[t0 + lane] = gelu_tanh(yr);
        yio[t0 + lane] = gelu_tanh(yi);
        __syncwarp();
    }
}

// ---------------- residual + complex LayerNorm over channels ----------------------
__global__ __launch_bounds__(256) void ln_kernel(int l,
    const float* __restrict__ gamma_r, const float* __restrict__ gamma_i,
    const float* __restrict__ beta_r,  const float* __restrict__ beta_i)
{
    int b  = blockIdx.y;
    int t0 = blockIdx.x * 32;
    int tt = threadIdx.x & 31;
    int gg = threadIdx.x >> 5;
    int t  = t0 + tt;

    float vr[32], vi[32];
    float sr = 0.f, qr = 0.f, si = 0.f, qi = 0.f;
#pragma unroll
    for (int j = 0; j < 32; j++) {
        int g = gg*32 + j;
        long off = ((long)b*DM + g)*TLEN + t;
        float r  = g_zr[off] + g_or[off];
        float i_ = g_zi[off] + g_oi[off];
        vr[j] = r; vi[j] = i_;
        sr += r;  qr = fmaf(r, r, qr);
        si += i_; qi = fmaf(i_, i_, qi);
    }
    __shared__ float red[4][8][32];
    red[0][gg][tt] = sr; red[1][gg][tt] = qr;
    red[2][gg][tt] = si; red[3][gg][tt] = qi;
    __syncthreads();
    float tsr = 0.f, tqr = 0.f, tsi = 0.f, tqi = 0.f;
#pragma unroll
    for (int k = 0; k < 8; k++) {
        tsr += red[0][k][tt]; tqr += red[1][k][tt];
        tsi += red[2][k][tt]; tqi += red[3][k][tt];
    }
    float mr  = tsr * (1.f/DM), mi_ = tsi * (1.f/DM);
    float var_r = tqr * (1.f/DM) - mr*mr;
    float var_i = tqi * (1.f/DM) - mi_*mi_;
    float rr = rsqrtf(var_r + 1e-5f);
    float ri = rsqrtf(var_i + 1e-5f);
#pragma unroll
    for (int j = 0; j < 32; j++) {
        int g = gg*32 + j;
        long off = ((long)b*DM + g)*TLEN + t;
        g_zr[off] = (vr[j] - mr)  * rr * gamma_r[l*DM + g] + beta_r[l*DM + g];
        g_zi[off] = (vi[j] - mi_) * ri * gamma_i[l*DM + g] + beta_i[l*DM + g];
    }
}

// ---------------- launch ------------------------------------------------------
extern "C" void kernel_launch(void* const* d_in, const int* in_sizes, int n_in,
                              void* d_out, int out_size)
{
    const float* x          = (const float*)d_in[0];
    const float* enc_Wr     = (const float*)d_in[1];
    const float* enc_Wi     = (const float*)d_in[2];
    const float* enc_br     = (const float*)d_in[3];
    const float* enc_bi     = (const float*)d_in[4];
    const float* log_dt     = (const float*)d_in[5];
    const float* log_A_real = (const float*)d_in[6];
    const float* A_imag     = (const float*)d_in[7];
    const float* C_r        = (const float*)d_in[8];
    const float* C_i        = (const float*)d_in[9];
    const float* Dvec       = (const float*)d_in[10];
    const float* out_Wr     = (const float*)d_in[11];
    const float* out_Wi     = (const float*)d_in[12];
    const float* out_br     = (const float*)d_in[13];
    const float* out_bi     = (const float*)d_in[14];
    const float* ln_gamma_r = (const float*)d_in[15];
    const float* ln_gamma_i = (const float*)d_in[16];
    const float* ln_beta_r  = (const float*)d_in[17];
    const float* ln_beta_i  = (const float*)d_in[18];
    const float* dec_Wr     = (const float*)d_in[19];
    const float* dec_Wi     = (const float*)d_in[20];
    const float* dec_br     = (const float*)d_in[21];
    const float* dec_bi     = (const float*)d_in[22];

    precompute_kernel<<<(NL*DM*NST + 255)/256, 256>>>(log_dt, log_A_real, A_imag, C_r, C_i);

    pack_out<<<(NL*DM*DM + 255)/256, 256>>>(out_Wr, out_Wi);
    pack_dec<<<(DM*GDEC + 255)/256, 256>>>(dec_Wr, dec_Wi);
    packA_enc<<<(int)(((long)512*KTE + 255)/256), 256>>>(enc_Wr, enc_Wi);
    conv_xe<<<dim3(32, KPE/64, BATCH), 128>>>(x);

    mma_enc<<<dim3(TLEN/64, 4, BATCH), 256>>>(enc_br, enc_bi);

    for (int l = 0; l < NL; l++) {
        scan_kernel<<<(BATCH*DM)/4, 128>>>(l, Dvec);
        outlin_gemm<<<dim3(TLEN/128, DM/64, BATCH), 256>>>(l, out_br, out_bi);
        ln_kernel<<<dim3(TLEN/32, BATCH), 256>>>(l, ln_gamma_r, ln_gamma_i, ln_beta_r, ln_beta_i);
    }

    decoder_gemm<<<dim3(TLEN/128, GDEC/64, BATCH), 256>>>(dec_br, dec_bi, (float4*)d_out);
}

// round 14
// speedup vs baseline: 1.1184x; 1.1184x over previous
#include <cuda_runtime.h>
#include <cuda_bf16.h>
#include <cstdint>
#include <math.h>

#define BATCH 8
#define DM    256
#define TLEN  2048
#define DIN   514
#define NL    4
#define NST   32
#define KPE   576
#define KPM   256
#define KTE   (6*KPE)   // 3456
#define KTM   (6*KPM)   // 1536

typedef unsigned long long u64;

// ---------------- scratch ----------------
__device__ __align__(16) float g_zr [BATCH*DM*TLEN];
__device__ __align__(16) float g_zi [BATCH*DM*TLEN];
__device__ __align__(16) float g_ygr[BATCH*DM*TLEN];
__device__ __align__(16) float g_ygi[BATCH*DM*TLEN];
__device__ __align__(16) float g_or [BATCH*DM*TLEN];
__device__ __align__(16) float g_oi [BATCH*DM*TLEN];
__device__ float g_ar [NL*DM*NST];
__device__ float g_ai [NL*DM*NST];
__device__ float g_cr [NL*DM*NST];
__device__ float g_ci [NL*DM*NST];
// X' operands: [b][t][K'] bf16 (6 K-blocks)
__device__ __align__(16) __nv_bfloat16 g_xe[(long)BATCH*TLEN*KTE];
__device__ __align__(16) __nv_bfloat16 g_xm[(long)BATCH*TLEN*KTM];
__device__ __align__(16) __nv_bfloat16 g_xd[(long)BATCH*TLEN*KTM];
// A operands: [m][K'] bf16, m = [R rows | I rows]
__device__ __align__(16) __nv_bfloat16 g_aenc[512*KTE];
__device__ __align__(16) __nv_bfloat16 g_aout[NL*512*KTM];
__device__ __align__(16) __nv_bfloat16 g_adec[1152*KTM];

// ---------------- helpers ----------------
__device__ __forceinline__ void mma16816(float* c, const uint32_t* a, uint32_t b0, uint32_t b1) {
    asm volatile("mma.sync.aligned.m16n8k16.row.col.f32.bf16.bf16.f32 "
                 "{%0,%1,%2,%3}, {%4,%5,%6,%7}, {%8,%9}, {%0,%1,%2,%3};"
                 : "+f"(c[0]), "+f"(c[1]), "+f"(c[2]), "+f"(c[3])
                 : "r"(a[0]), "r"(a[1]), "r"(a[2]), "r"(a[3]), "r"(b0), "r"(b1));
}
__device__ __forceinline__ float gelu_tanh(float x) {
    float x3 = x * x * x;
    float t  = 0.7978845608028654f * fmaf(0.044715f, x3, x);
    float th;
    asm("tanh.approx.f32 %0, %1;" : "=f"(th) : "f"(t));
    return 0.5f * x * (1.0f + th);
}

// ---------------- S4D coefficient precompute ----------------
__global__ void precompute_kernel(const float* __restrict__ log_dt,
                                  const float* __restrict__ log_A_real,
                                  const float* __restrict__ A_imag,
                                  const float* __restrict__ C_r,
                                  const float* __restrict__ C_i)
{
    int idx = blockIdx.x * blockDim.x + threadIdx.x;
    if (idx >= NL*DM*NST) return;
    int h = (idx / NST) % DM;
    int l = idx / (NST*DM);
    double dt  = exp((double)log_dt[l*DM + h]);
    double Are = -exp((double)log_A_real[idx]);
    double Aim = (double)A_imag[idx];
    double er  = exp(Are * dt);
    double arr = er * cos(Aim * dt);
    double aii = er * sin(Aim * dt);
    g_ar[idx] = (float)arr;
    g_ai[idx] = (float)aii;
    double e1r = arr - 1.0, e1i = aii;
    double den = Are*Are + Aim*Aim;
    double qr  = (e1r*Are + e1i*Aim) / den;
    double qi  = (e1i*Are - e1r*Aim) / den;
    double cr  = (double)C_r[idx], ci = (double)C_i[idx];
    g_cr[idx] = (float)(cr*qr - ci*qi);
    g_ci[idx] = (float)(cr*qi + ci*qr);
}

// ---------------- A prepack (validated R11 math; symbols resolved ON DEVICE) -----
// Row m < Mr (R rows, g=m):       [WrH, WrH, WrL, -WiH, -WiH, -WiL]
// Row m >= Mr (I rows, g=m-Mr):   [WiH, WiH, WiL,  WrH,  WrH,  WrL]
__global__ void packA(const float* __restrict__ Wr, const float* __restrict__ Wi,
                      int ld, int Greal, int Kreal, int Kp, int Mr,
                      int which, int layer, long total)
{
    long idx = (long)blockIdx.x*blockDim.x + threadIdx.x;
    if (idx >= total) return;
    __nv_bfloat16* dst = (which == 0) ? g_aenc
                       : (which == 1) ? (g_aout + (long)layer*512*KTM) : g_adec;
    int Kt = 6*Kp;
    int m  = (int)(idx / Kt);
    int kp = (int)(idx % Kt);
    int bk = kp / Kp, k = kp % Kp;
    int isR = m < Mr;
    int g = isR ? m : m - Mr;
    float w = 0.f;
    if (g < Greal && k < Kreal) {
        const float* W = isR ? (bk < 3 ? Wr : Wi) : (bk < 3 ? Wi : Wr);
        float s = (isR && bk >= 3) ? -1.f : 1.f;
        w = s * W[(long)g*ld + k];
    }
    __nv_bfloat16 h = __float2bfloat16(w);
    if (bk % 3 == 2) h = __float2bfloat16(w - __bfloat162float(h));
    dst[idx] = h;
}

// ---------------- X convert (validated R11 math; symbols resolved ON DEVICE) -----
// B blocks: [XrH, XrL, XrH, XiH, XiL, XiH]; dst[b][t][K']
__global__ __launch_bounds__(128) void conv_x(int mode, const float* __restrict__ xsrc,
                                              int Kp, int Kreal)
{
    __shared__ float sre[64][65], sim[64][65];
    int tt = blockIdx.x, chunk = blockIdx.y, b = blockIdx.z;
    int Kt = 6*Kp;
    int tid = threadIdx.x;
    __nv_bfloat16* dst = (mode == 0) ? g_xe : (mode == 1) ? g_xm : g_xd;
    for (int idx = tid; idx < 4096; idx += 128) {
        int k = idx >> 6, t = idx & 63;
        int kg = chunk*64 + k, tg = tt*64 + t;
        float re = 0.f, im = 0.f;
        if (kg < Kreal) {
            if (mode == 0) {
                const float* p = xsrc + ((((long)b*DIN + kg)*TLEN + tg) << 1);
                re = p[0]; im = p[1];
            } else {
                long off = ((long)b*DM + kg)*TLEN + tg;
                if (mode == 1) { re = g_ygr[off]; im = g_ygi[off]; }
                else           { re = g_zr[off];  im = g_zi[off];  }
            }
        }
        sre[k][t] = re; sim[k][t] = im;
    }
    __syncthreads();
    for (int idx = tid; idx < 2048; idx += 128) {
        int t = idx >> 5, k2 = (idx & 31)*2;
        float r0 = sre[k2][t],   i0 = sim[k2][t];
        float r1 = sre[k2+1][t], i1 = sim[k2+1][t];
        __nv_bfloat16 rh0 = __float2bfloat16(r0), rh1 = __float2bfloat16(r1);
        __nv_bfloat16 rl0 = __float2bfloat16(r0 - __bfloat162float(rh0));
        __nv_bfloat16 rl1 = __float2bfloat16(r1 - __bfloat162float(rh1));
        __nv_bfloat16 ih0 = __float2bfloat16(i0), ih1 = __float2bfloat16(i1);
        __nv_bfloat16 il0 = __float2bfloat16(i0 - __bfloat162float(ih0));
        __nv_bfloat16 il1 = __float2bfloat16(i1 - __bfloat162float(ih1));
        uint32_t RH = ((uint32_t)*(uint16_t*)&rh1 << 16) | *(uint16_t*)&rh0;
        uint32_t RL = ((uint32_t)*(uint16_t*)&rl1 << 16) | *(uint16_t*)&rl0;
        uint32_t IH = ((uint32_t)*(uint16_t*)&ih1 << 16) | *(uint16_t*)&ih0;
        uint32_t IL = ((uint32_t)*(uint16_t*)&il1 << 16) | *(uint16_t*)&il0;
        long base = ((long)b*TLEN + tt*64 + t)*Kt + chunk*64 + k2;
        *(uint32_t*)(dst + base)        = RH;
        *(uint32_t*)(dst + base + Kp)   = RL;
        *(uint32_t*)(dst + base + 2*Kp) = RH;
        *(uint32_t*)(dst + base + 3*Kp) = IH;
        *(uint32_t*)(dst + base + 4*Kp) = IL;
        *(uint32_t*)(dst + base + 5*Kp) = IH;
    }
}

// ---------------- register-prefetch MMA GEMM (symbols resolved ON DEVICE) --------
// C[M][2048] = A[M][Kt] * X^T per b. CTA 128m x 64n, BK=32, 8 warps @ 64x16.
__global__ __launch_bounds__(256) void mma_gemm(int which, int layer,
    const float* __restrict__ bR, const float* __restrict__ bI,
    float* __restrict__ dout)
{
    __shared__ __nv_bfloat16 sA[128][40];
    __shared__ __nv_bfloat16 sB[64][40];
    const __nv_bfloat16 *A, *X;
    int Kt, Mr;
    if (which == 0)      { A = g_aenc; X = g_xe; Kt = KTE; Mr = 256; }
    else if (which == 1) { A = g_aout + (long)layer*512*KTM; X = g_xm; Kt = KTM; Mr = 256; }
    else                 { A = g_adec; X = g_xd; Kt = KTM; Mr = 576; }
    float* outR = (which == 0) ? g_zr : g_or;
    float* outI = (which == 0) ? g_zi : g_oi;

    int tid = threadIdx.x;
    int t0 = blockIdx.x*64, m0 = blockIdx.y*128, b = blockIdx.z;
    int nc = Kt >> 5;
    const __nv_bfloat16* Xb = X + (long)b*TLEN*Kt;
    int wid = tid >> 5, lane = tid & 31;
    int wg = (wid >> 2)*64, wt = (wid & 3)*16;
    int gid = lane >> 2, tig = lane & 3;
    int rowb = tid >> 4, colb = (tid & 15)*2;    // load mapping

    float acc[4][2][4];
#pragma unroll
    for (int i = 0; i < 4; i++)
#pragma unroll
        for (int j = 0; j < 2; j++)
#pragma unroll
            for (int r = 0; r < 4; r++) acc[i][j][r] = 0.f;

    const __nv_bfloat16* Abase = A  + (long)m0*Kt + colb;
    const __nv_bfloat16* Bbase = Xb + (long)t0*Kt + colb;

    uint32_t ra[8], rb[4];
#pragma unroll
    for (int q = 0; q < 8; q++)
        ra[q] = *(const uint32_t*)(Abase + (long)(rowb + q*16)*Kt);
#pragma unroll
    for (int q = 0; q < 4; q++)
        rb[q] = *(const uint32_t*)(Bbase + (long)(rowb + q*16)*Kt);

    for (int c = 0; c < nc; c++) {
#pragma unroll
        for (int q = 0; q < 8; q++)
            *(uint32_t*)&sA[rowb + q*16][colb] = ra[q];
#pragma unroll
        for (int q = 0; q < 4; q++)
            *(uint32_t*)&sB[rowb + q*16][colb] = rb[q];
        __syncthreads();
        if (c + 1 < nc) {
            const __nv_bfloat16* An = Abase + (c+1)*32;
            const __nv_bfloat16* Bn = Bbase + (c+1)*32;
#pragma unroll
            for (int q = 0; q < 8; q++)
                ra[q] = *(const uint32_t*)(An + (long)(rowb + q*16)*Kt);
#pragma unroll
            for (int q = 0; q < 4; q++)
                rb[q] = *(const uint32_t*)(Bn + (long)(rowb + q*16)*Kt);
        }
#pragma unroll
        for (int kk = 0; kk < 2; kk++) {
            int cb = kk*16 + tig*2;
            uint32_t af[4][4];
#pragma unroll
            for (int mt = 0; mt < 4; mt++) {
                int r = wg + mt*16 + gid;
                af[mt][0] = *(uint32_t*)&sA[r][cb];
                af[mt][1] = *(uint32_t*)&sA[r+8][cb];
                af[mt][2] = *(uint32_t*)&sA[r][cb+8];
                af[mt][3] = *(uint32_t*)&sA[r+8][cb+8];
            }
            uint32_t bf[2][2];
#pragma unroll
            for (int nt = 0; nt < 2; nt++) {
                int n = wt + nt*8 + gid;
                bf[nt][0] = *(uint32_t*)&sB[n][cb];
                bf[nt][1] = *(uint32_t*)&sB[n][cb+8];
            }
#pragma unroll
            for (int mt = 0; mt < 4; mt++)
#pragma unroll
                for (int nt = 0; nt < 2; nt++)
                    mma16816(acc[mt][nt], af[mt], bf[nt][0], bf[nt][1]);
        }
        __syncthreads();
    }

#pragma unroll
    for (int mt = 0; mt < 4; mt++) {
#pragma unroll
        for (int nt = 0; nt < 2; nt++) {
            int t = t0 + wt + nt*8 + tig*2;
#pragma unroll
            for (int h = 0; h < 2; h++) {
                int mm = m0 + wg + mt*16 + gid + h*8;
                float v0 = acc[mt][nt][h*2], v1 = acc[mt][nt][h*2+1];
                int isR = mm < Mr;
                int g = isR ? mm : mm - Mr;
                if (which == 2) {
                    if (g < DIN) {
                        float bb = isR ? bR[g] : bI[g];
                        float* p = dout + ((((long)b*DIN + g)*TLEN + t) << 1) + (isR ? 0 : 1);
                        p[0] = v0 + bb; p[2] = v1 + bb;
                    }
                } else {
                    float bb = isR ? bR[g] : bI[g];
                    float* base = isR ? outR : outI;
                    *(float2*)&base[((long)b*DM + g)*TLEN + t] = make_float2(v0 + bb, v1 + bb);
                }
            }
        }
    }
}

// ---------------- per-layer S4D scan + D-skip + gelu (warp = one (b,h)) ----------
__global__ __launch_bounds__(128) void scan_kernel(int layer, const float* __restrict__ Dvec)
{
    __shared__ float2 uS[4][32];
    __shared__ float2 prodS[4][32][34];
    int wid  = threadIdx.x >> 5;
    int lane = threadIdx.x & 31;
    int ch = blockIdx.x * 4 + wid;
    int b  = ch >> 8;
    int h  = ch & 255;
    int pidx = (layer*DM + h)*NST + lane;
    float ar = g_ar[pidx], ai = g_ai[pidx];
    float cr = g_cr[pidx], ci = g_ci[pidx];
    float Dh = Dvec[layer*DM + h];
    long base = ((long)b*DM + h)*TLEN;
    const float* zr = g_zr + base;
    const float* zi = g_zi + base;
    float* yro = g_ygr + base;
    float* yio = g_ygi + base;

    float sr = 0.f, si = 0.f;
    for (int t0 = 0; t0 < TLEN; t0 += 32) {
        float ur_l = zr[t0 + lane];
        float ui_l = zi[t0 + lane];
        uS[wid][lane] = make_float2(ur_l, ui_l);
        __syncwarp();
#pragma unroll
        for (int j = 0; j < 32; j++) {
            float2 u = uS[wid][j];
            float nsr = fmaf(ar, sr, u.x); nsr = fmaf(-ai, si, nsr);
            float nsi = fmaf(ar, si, u.y); nsi = fmaf( ai, sr, nsi);
            sr = nsr; si = nsi;
            float pr = cr * sr; pr = fmaf(-ci, si, pr);
            float pi = cr * si; pi = fmaf( ci, sr, pi);
            prodS[wid][j][lane] = make_float2(pr, pi);
        }
        __syncwarp();
        float yr = 0.f, yi = 0.f;
#pragma unroll
        for (int q = 0; q < 32; q++) {
            float2 v = prodS[wid][lane][q];
            yr += v.x; yi += v.y;
        }
        yr = fmaf(Dh, ur_l, yr);
        yi = fmaf(Dh, ui_l, yi);
        yro[t0 + lane] = gelu_tanh(yr);
        yio[t0 + lane] = gelu_tanh(yi);
        __syncwarp();
    }
}

// ---------------- residual + complex LayerNorm over channels ----------------------
__global__ __launch_bounds__(256) void ln_kernel(int l,
    const float* __restrict__ gamma_r, const float* __restrict__ gamma_i,
    const float* __restrict__ beta_r,  const float* __restrict__ beta_i)
{
    int b  = blockIdx.y;
    int t0 = blockIdx.x * 32;
    int tt = threadIdx.x & 31;
    int gg = threadIdx.x >> 5;
    int t  = t0 + tt;

    float vr[32], vi[32];
    float sr = 0.f, qr = 0.f, si = 0.f, qi = 0.f;
#pragma unroll
    for (int j = 0; j < 32; j++) {
        int g = gg*32 + j;
        long off = ((long)b*DM + g)*TLEN + t;
        float r  = g_zr[off] + g_or[off];
        float i_ = g_zi[off] + g_oi[off];
        vr[j] = r; vi[j] = i_;
        sr += r;  qr = fmaf(r, r, qr);
        si += i_; qi = fmaf(i_, i_, qi);
    }
    __shared__ float red[4][8][32];
    red[0][gg][tt] = sr; red[1][gg][tt] = qr;
    red[2][gg][tt] = si; red[3][gg][tt] = qi;
    __syncthreads();
    float tsr = 0.f, tqr = 0.f, tsi = 0.f, tqi = 0.f;
#pragma unroll
    for (int k = 0; k < 8; k++) {
        tsr += red[0][k][tt]; tqr += red[1][k][tt];
        tsi += red[2][k][tt]; tqi += red[3][k][tt];
    }
    float mr  = tsr * (1.f/DM), mi_ = tsi * (1.f/DM);
    float var_r = tqr * (1.f/DM) - mr*mr;
    float var_i = tqi * (1.f/DM) - mi_*mi_;
    float rr = rsqrtf(var_r + 1e-5f);
    float ri = rsqrtf(var_i + 1e-5f);
#pragma unroll
    for (int j = 0; j < 32; j++) {
        int g = gg*32 + j;
        long off = ((long)b*DM + g)*TLEN + t;
        g_zr[off] = (vr[j] - mr)  * rr * gamma_r[l*DM + g] + beta_r[l*DM + g];
        g_zi[off] = (vi[j] - mi_) * ri * gamma_i[l*DM + g] + beta_i[l*DM + g];
    }
}

// ---------------- launch ------------------------------------------------------
extern "C" void kernel_launch(void* const* d_in, const int* in_sizes, int n_in,
                              void* d_out, int out_size)
{
    const float* x          = (const float*)d_in[0];
    const float* enc_Wr     = (const float*)d_in[1];
    const float* enc_Wi     = (const float*)d_in[2];
    const float* enc_br     = (const float*)d_in[3];
    const float* enc_bi     = (const float*)d_in[4];
    const float* log_dt     = (const float*)d_in[5];
    const float* log_A_real = (const float*)d_in[6];
    const float* A_imag     = (const float*)d_in[7];
    const float* C_r        = (const float*)d_in[8];
    const float* C_i        = (const float*)d_in[9];
    const float* Dvec       = (const float*)d_in[10];
    const float* out_Wr     = (const float*)d_in[11];
    const float* out_Wi     = (const float*)d_in[12];
    const float* out_br     = (const float*)d_in[13];
    const float* out_bi     = (const float*)d_in[14];
    const float* ln_gamma_r = (const float*)d_in[15];
    const float* ln_gamma_i = (const float*)d_in[16];
    const float* ln_beta_r  = (const float*)d_in[17];
    const float* ln_beta_i  = (const float*)d_in[18];
    const float* dec_Wr     = (const float*)d_in[19];
    const float* dec_Wi     = (const float*)d_in[20];
    const float* dec_br     = (const float*)d_in[21];
    const float* dec_bi     = (const float*)d_in[22];

    precompute_kernel<<<(NL*DM*NST + 255)/256, 256>>>(log_dt, log_A_real, A_imag, C_r, C_i);

    long te = (long)512*KTE;
    packA<<<(int)((te + 255)/256), 256>>>(enc_Wr, enc_Wi, DIN, DM, DIN, KPE, 256, 0, 0, te);
    long to = (long)512*KTM;
    for (int l = 0; l < NL; l++)
        packA<<<(int)((to + 255)/256), 256>>>(out_Wr + (long)l*DM*DM, out_Wi + (long)l*DM*DM,
                                              DM, DM, DM, KPM, 256, 1, l, to);
    long td = (long)1152*KTM;
    packA<<<(int)((td + 255)/256), 256>>>(dec_Wr, dec_Wi, DM, DIN, DM, KPM, 576, 2, 0, td);

    conv_x<<<dim3(32, KPE/64, BATCH), 128>>>(0, x, KPE, DIN);
    mma_gemm<<<dim3(32, 4, BATCH), 256>>>(0, 0, enc_br, enc_bi, nullptr);

    for (int l = 0; l < NL; l++) {
        scan_kernel<<<(BATCH*DM)/4, 128>>>(l, Dvec);
        conv_x<<<dim3(32, KPM/64, BATCH), 128>>>(1, nullptr, KPM, DM);
        mma_gemm<<<dim3(32, 4, BATCH), 256>>>(1, l, out_br + l*DM, out_bi + l*DM, nullptr);
        ln_kernel<<<dim3(TLEN/32, BATCH), 256>>>(l, ln_gamma_r, ln_gamma_i, ln_beta_r, ln_beta_i);
    }

    conv_x<<<dim3(32, KPM/64, BATCH), 128>>>(2, nullptr, KPM, DM);
    mma_gemm<<<dim3(32, 9, BATCH), 256>>>(2, 0, dec_br, dec_bi, (float*)d_out);
}

// round 15
// speedup vs baseline: 1.3811x; 1.2349x over previous
#include <cuda_runtime.h>
#include <cuda_bf16.h>
#include <cstdint>
#include <math.h>

#define BATCH 8
#define DM    256
#define TLEN  2048
#define DIN   514
#define NL    4
#define NST   32
#define KPE   576
#define KPM   256
#define KTE   (6*KPE)   // 3456
#define KTM   (6*KPM)   // 1536

typedef unsigned long long u64;

// ---------------- scratch ----------------
__device__ __align__(16) float g_zr [BATCH*DM*TLEN];
__device__ __align__(16) float g_zi [BATCH*DM*TLEN];
__device__ __align__(16) float g_ygr[BATCH*DM*TLEN];
__device__ __align__(16) float g_ygi[BATCH*DM*TLEN];
__device__ __align__(16) float g_or [BATCH*DM*TLEN];
__device__ __align__(16) float g_oi [BATCH*DM*TLEN];
__device__ float g_ar [NL*DM*NST];
__device__ float g_ai [NL*DM*NST];
__device__ float g_cr [NL*DM*NST];
__device__ float g_ci [NL*DM*NST];
// X' operands: [b][t][K'] bf16 (6 K-blocks)
__device__ __align__(16) __nv_bfloat16 g_xe[(long)BATCH*TLEN*KTE];
__device__ __align__(16) __nv_bfloat16 g_xm[(long)BATCH*TLEN*KTM];
__device__ __align__(16) __nv_bfloat16 g_xd[(long)BATCH*TLEN*KTM];
// A operands: [m][K'] bf16, m = [R rows | I rows]
__device__ __align__(16) __nv_bfloat16 g_aenc[512*KTE];
__device__ __align__(16) __nv_bfloat16 g_aout[NL*512*KTM];
__device__ __align__(16) __nv_bfloat16 g_adec[1152*KTM];

// ---------------- helpers ----------------
__device__ __forceinline__ void mma16816(float* c, const uint32_t* a, uint32_t b0, uint32_t b1) {
    asm volatile("mma.sync.aligned.m16n8k16.row.col.f32.bf16.bf16.f32 "
                 "{%0,%1,%2,%3}, {%4,%5,%6,%7}, {%8,%9}, {%0,%1,%2,%3};"
                 : "+f"(c[0]), "+f"(c[1]), "+f"(c[2]), "+f"(c[3])
                 : "r"(a[0]), "r"(a[1]), "r"(a[2]), "r"(a[3]), "r"(b0), "r"(b1));
}
__device__ __forceinline__ float gelu_tanh(float x) {
    float x3 = x * x * x;
    float t  = 0.7978845608028654f * fmaf(0.044715f, x3, x);
    float th;
    asm("tanh.approx.f32 %0, %1;" : "=f"(th) : "f"(t));
    return 0.5f * x * (1.0f + th);
}

// ---------------- S4D coefficient precompute ----------------
__global__ void precompute_kernel(const float* __restrict__ log_dt,
                                  const float* __restrict__ log_A_real,
                                  const float* __restrict__ A_imag,
                                  const float* __restrict__ C_r,
                                  const float* __restrict__ C_i)
{
    int idx = blockIdx.x * blockDim.x + threadIdx.x;
    if (idx >= NL*DM*NST) return;
    int h = (idx / NST) % DM;
    int l = idx / (NST*DM);
    double dt  = exp((double)log_dt[l*DM + h]);
    double Are = -exp((double)log_A_real[idx]);
    double Aim = (double)A_imag[idx];
    double er  = exp(Are * dt);
    double arr = er * cos(Aim * dt);
    double aii = er * sin(Aim * dt);
    g_ar[idx] = (float)arr;
    g_ai[idx] = (float)aii;
    double e1r = arr - 1.0, e1i = aii;
    double den = Are*Are + Aim*Aim;
    double qr  = (e1r*Are + e1i*Aim) / den;
    double qi  = (e1i*Are - e1r*Aim) / den;
    double cr  = (double)C_r[idx], ci = (double)C_i[idx];
    g_cr[idx] = (float)(cr*qr - ci*qi);
    g_ci[idx] = (float)(cr*qi + ci*qr);
}

// ---------------- A prepack (validated; symbols resolved ON DEVICE) --------------
// Row m < Mr (R rows, g=m):       [WrH, WrH, WrL, -WiH, -WiH, -WiL]
// Row m >= Mr (I rows, g=m-Mr):   [WiH, WiH, WiL,  WrH,  WrH,  WrL]
// which==1 packs ALL NL layers in one launch (layer from linear index).
__global__ void packA(const float* __restrict__ Wr, const float* __restrict__ Wi,
                      int ld, int Greal, int Kreal, int Kp, int Mr,
                      int which, long total)
{
    long idx = (long)blockIdx.x*blockDim.x + threadIdx.x;
    if (idx >= total) return;
    __nv_bfloat16* dst;
    const float *WrL_, *WiL_;
    long lidx = idx;
    if (which == 1) {
        int layer = (int)(idx / ((long)512*KTM));
        lidx = idx % ((long)512*KTM);
        dst = g_aout + (long)layer*512*KTM;
        WrL_ = Wr + (long)layer*DM*DM;
        WiL_ = Wi + (long)layer*DM*DM;
    } else {
        dst = (which == 0) ? g_aenc : g_adec;
        WrL_ = Wr; WiL_ = Wi;
    }
    int Kt = 6*Kp;
    int m  = (int)(lidx / Kt);
    int kp = (int)(lidx % Kt);
    int bk = kp / Kp, k = kp % Kp;
    int isR = m < Mr;
    int g = isR ? m : m - Mr;
    float w = 0.f;
    if (g < Greal && k < Kreal) {
        const float* W = isR ? (bk < 3 ? WrL_ : WiL_) : (bk < 3 ? WiL_ : WrL_);
        float s = (isR && bk >= 3) ? -1.f : 1.f;
        w = s * W[(long)g*ld + k];
    }
    __nv_bfloat16 h = __float2bfloat16(w);
    if (bk % 3 == 2) h = __float2bfloat16(w - __bfloat162float(h));
    dst[lidx] = h;
}

// ---------------- X convert (validated; symbols resolved ON DEVICE) --------------
// B blocks: [XrH, XrL, XrH, XiH, XiL, XiH]; dst[b][t][K']
__global__ __launch_bounds__(128) void conv_x(int mode, const float* __restrict__ xsrc,
                                              int Kp, int Kreal)
{
    __shared__ float sre[64][65], sim[64][65];
    int tt = blockIdx.x, chunk = blockIdx.y, b = blockIdx.z;
    int Kt = 6*Kp;
    int tid = threadIdx.x;
    __nv_bfloat16* dst = (mode == 0) ? g_xe : (mode == 1) ? g_xm : g_xd;
    for (int idx = tid; idx < 4096; idx += 128) {
        int k = idx >> 6, t = idx & 63;
        int kg = chunk*64 + k, tg = tt*64 + t;
        float re = 0.f, im = 0.f;
        if (kg < Kreal) {
            if (mode == 0) {
                const float* p = xsrc + ((((long)b*DIN + kg)*TLEN + tg) << 1);
                re = p[0]; im = p[1];
            } else {
                long off = ((long)b*DM + kg)*TLEN + tg;
                if (mode == 1) { re = g_ygr[off]; im = g_ygi[off]; }
                else           { re = g_zr[off];  im = g_zi[off];  }
            }
        }
        sre[k][t] = re; sim[k][t] = im;
    }
    __syncthreads();
    for (int idx = tid; idx < 2048; idx += 128) {
        int t = idx >> 5, k2 = (idx & 31)*2;
        float r0 = sre[k2][t],   i0 = sim[k2][t];
        float r1 = sre[k2+1][t], i1 = sim[k2+1][t];
        __nv_bfloat16 rh0 = __float2bfloat16(r0), rh1 = __float2bfloat16(r1);
        __nv_bfloat16 rl0 = __float2bfloat16(r0 - __bfloat162float(rh0));
        __nv_bfloat16 rl1 = __float2bfloat16(r1 - __bfloat162float(rh1));
        __nv_bfloat16 ih0 = __float2bfloat16(i0), ih1 = __float2bfloat16(i1);
        __nv_bfloat16 il0 = __float2bfloat16(i0 - __bfloat162float(ih0));
        __nv_bfloat16 il1 = __float2bfloat16(i1 - __bfloat162float(ih1));
        uint32_t RH = ((uint32_t)*(uint16_t*)&rh1 << 16) | *(uint16_t*)&rh0;
        uint32_t RL = ((uint32_t)*(uint16_t*)&rl1 << 16) | *(uint16_t*)&rl0;
        uint32_t IH = ((uint32_t)*(uint16_t*)&ih1 << 16) | *(uint16_t*)&ih0;
        uint32_t IL = ((uint32_t)*(uint16_t*)&il1 << 16) | *(uint16_t*)&il0;
        long base = ((long)b*TLEN + tt*64 + t)*Kt + chunk*64 + k2;
        *(uint32_t*)(dst + base)        = RH;
        *(uint32_t*)(dst + base + Kp)   = RL;
        *(uint32_t*)(dst + base + 2*Kp) = RH;
        *(uint32_t*)(dst + base + 3*Kp) = IH;
        *(uint32_t*)(dst + base + 4*Kp) = IL;
        *(uint32_t*)(dst + base + 5*Kp) = IH;
    }
}

// ---------------- register-prefetch + smem-double-buffer MMA GEMM ----------------
// C[M][2048] = A[M][Kt] * X^T per b. CTA 128m x 128n, BK=32, 8 warps @ 64x32.
// One __syncthreads per chunk: STS(c+1)->buf^1 is safe after sync(c) because
// compute(c-1) (last reader of buf^1) completed before sync(c).
__global__ __launch_bounds__(256, 2) void mma_gemm(int which, int layer,
    const float* __restrict__ bR, const float* __restrict__ bI,
    float* __restrict__ dout)
{
    __shared__ __nv_bfloat16 sA[2][128][40];
    __shared__ __nv_bfloat16 sB[2][128][40];
    const __nv_bfloat16 *A, *X;
    int Kt, Mr;
    if (which == 0)      { A = g_aenc; X = g_xe; Kt = KTE; Mr = 256; }
    else if (which == 1) { A = g_aout + (long)layer*512*KTM; X = g_xm; Kt = KTM; Mr = 256; }
    else                 { A = g_adec; X = g_xd; Kt = KTM; Mr = 576; }
    float* outR = (which == 0) ? g_zr : g_or;
    float* outI = (which == 0) ? g_zi : g_oi;

    int tid = threadIdx.x;
    int t0 = blockIdx.x*128, m0 = blockIdx.y*128, b = blockIdx.z;
    int nc = Kt >> 5;
    const __nv_bfloat16* Xb = X + (long)b*TLEN*Kt;
    int wid = tid >> 5, lane = tid & 31;
    int wg = (wid >> 2)*64, wt = (wid & 3)*32;
    int gid = lane >> 2, tig = lane & 3;
    int rowb = tid >> 4, colb = (tid & 15)*2;    // load mapping (16 rows x 32 cols/pass)

    float acc[4][4][4];
#pragma unroll
    for (int i = 0; i < 4; i++)
#pragma unroll
        for (int j = 0; j < 4; j++)
#pragma unroll
            for (int r = 0; r < 4; r++) acc[i][j][r] = 0.f;

    const __nv_bfloat16* Abase = A  + ((long)m0 + rowb)*Kt + colb;
    const __nv_bfloat16* Bbase = Xb + ((long)t0 + rowb)*Kt + colb;

    uint32_t ra[8], rb[8];
#pragma unroll
    for (int q = 0; q < 8; q++) ra[q] = *(const uint32_t*)(Abase + (long)q*16*Kt);
#pragma unroll
    for (int q = 0; q < 8; q++) rb[q] = *(const uint32_t*)(Bbase + (long)q*16*Kt);

    for (int c = 0; c < nc; c++) {
        int buf = c & 1;
#pragma unroll
        for (int q = 0; q < 8; q++) *(uint32_t*)&sA[buf][rowb + q*16][colb] = ra[q];
#pragma unroll
        for (int q = 0; q < 8; q++) *(uint32_t*)&sB[buf][rowb + q*16][colb] = rb[q];
        __syncthreads();
        if (c + 1 < nc) {
            const __nv_bfloat16* An = Abase + (c+1)*32;
            const __nv_bfloat16* Bn = Bbase + (c+1)*32;
#pragma unroll
            for (int q = 0; q < 8; q++) ra[q] = *(const uint32_t*)(An + (long)q*16*Kt);
#pragma unroll
            for (int q = 0; q < 8; q++) rb[q] = *(const uint32_t*)(Bn + (long)q*16*Kt);
        }
#pragma unroll
        for (int kk = 0; kk < 2; kk++) {
            int cb = kk*16 + tig*2;
            uint32_t af[4][4];
#pragma unroll
            for (int mt = 0; mt < 4; mt++) {
                int r = wg + mt*16 + gid;
                af[mt][0] = *(uint32_t*)&sA[buf][r][cb];
                af[mt][1] = *(uint32_t*)&sA[buf][r+8][cb];
                af[mt][2] = *(uint32_t*)&sA[buf][r][cb+8];
                af[mt][3] = *(uint32_t*)&sA[buf][r+8][cb+8];
            }
            uint32_t bf[4][2];
#pragma unroll
            for (int nt = 0; nt < 4; nt++) {
                int n = wt + nt*8 + gid;
                bf[nt][0] = *(uint32_t*)&sB[buf][n][cb];
                bf[nt][1] = *(uint32_t*)&sB[buf][n][cb+8];
            }
#pragma unroll
            for (int mt = 0; mt < 4; mt++)
#pragma unroll
                for (int nt = 0; nt < 4; nt++)
                    mma16816(acc[mt][nt], af[mt], bf[nt][0], bf[nt][1]);
        }
    }

#pragma unroll
    for (int mt = 0; mt < 4; mt++) {
#pragma unroll
        for (int nt = 0; nt < 4; nt++) {
            int t = t0 + wt + nt*8 + tig*2;
#pragma unroll
            for (int h = 0; h < 2; h++) {
                int mm = m0 + wg + mt*16 + gid + h*8;
                float v0 = acc[mt][nt][h*2], v1 = acc[mt][nt][h*2+1];
                int isR = mm < Mr;
                int g = isR ? mm : mm - Mr;
                if (which == 2) {
                    if (g < DIN) {
                        float bb = isR ? bR[g] : bI[g];
                        float* p = dout + ((((long)b*DIN + g)*TLEN + t) << 1) + (isR ? 0 : 1);
                        p[0] = v0 + bb; p[2] = v1 + bb;
                    }
                } else {
                    float bb = isR ? bR[g] : bI[g];
                    float* base = isR ? outR : outI;
                    *(float2*)&base[((long)b*DM + g)*TLEN + t] = make_float2(v0 + bb, v1 + bb);
                }
            }
        }
    }
}

// ---------------- per-layer S4D scan + D-skip + gelu (warp = one (b,h)) ----------
__global__ __launch_bounds__(128) void scan_kernel(int layer, const float* __restrict__ Dvec)
{
    __shared__ float2 uS[4][32];
    __shared__ float2 prodS[4][32][34];
    int wid  = threadIdx.x >> 5;
    int lane = threadIdx.x & 31;
    int ch = blockIdx.x * 4 + wid;
    int b  = ch >> 8;
    int h  = ch & 255;
    int pidx = (layer*DM + h)*NST + lane;
    float ar = g_ar[pidx], ai = g_ai[pidx];
    float cr = g_cr[pidx], ci = g_ci[pidx];
    float Dh = Dvec[layer*DM + h];
    long base = ((long)b*DM + h)*TLEN;
    const float* zr = g_zr + base;
    const float* zi = g_zi + base;
    float* yro = g_ygr + base;
    float* yio = g_ygi + base;

    float sr = 0.f, si = 0.f;
    for (int t0 = 0; t0 < TLEN; t0 += 32) {
        float ur_l = zr[t0 + lane];
        float ui_l = zi[t0 + lane];
        uS[wid][lane] = make_float2(ur_l, ui_l);
        __syncwarp();
#pragma unroll
        for (int j = 0; j < 32; j++) {
            float2 u = uS[wid][j];
            float nsr = fmaf(ar, sr, u.x); nsr = fmaf(-ai, si, nsr);
            float nsi = fmaf(ar, si, u.y); nsi = fmaf( ai, sr, nsi);
            sr = nsr; si = nsi;
            float pr = cr * sr; pr = fmaf(-ci, si, pr);
            float pi = cr * si; pi = fmaf( ci, sr, pi);
            prodS[wid][j][lane] = make_float2(pr, pi);
        }
        __syncwarp();
        float yr = 0.f, yi = 0.f;
#pragma unroll
        for (int q = 0; q < 32; q++) {
            float2 v = prodS[wid][lane][q];
            yr += v.x; yi += v.y;
        }
        yr = fmaf(Dh, ur_l, yr);
        yi = fmaf(Dh, ui_l, yi);
        yro[t0 + lane] = gelu_tanh(yr);
        yio[t0 + lane] = gelu_tanh(yi);
        __syncwarp();
    }
}

// ---------------- residual + complex LayerNorm over channels ----------------------
__global__ __launch_bounds__(256) void ln_kernel(int l,
    const float* __restrict__ gamma_r, const float* __restrict__ gamma_i,
    const float* __restrict__ beta_r,  const float* __restrict__ beta_i)
{
    int b  = blockIdx.y;
    int t0 = blockIdx.x * 32;
    int tt = threadIdx.x & 31;
    int gg = threadIdx.x >> 5;
    int t  = t0 + tt;

    float vr[32], vi[32];
    float sr = 0.f, qr = 0.f, si = 0.f, qi = 0.f;
#pragma unroll
    for (int j = 0; j < 32; j++) {
        int g = gg*32 + j;
        long off = ((long)b*DM + g)*TLEN + t;
        float r  = g_zr[off] + g_or[off];
        float i_ = g_zi[off] + g_oi[off];
        vr[j] = r; vi[j] = i_;
        sr += r;  qr = fmaf(r, r, qr);
        si += i_; qi = fmaf(i_, i_, qi);
    }
    __shared__ float red[4][8][32];
    red[0][gg][tt] = sr; red[1][gg][tt] = qr;
    red[2][gg][tt] = si; red[3][gg][tt] = qi;
    __syncthreads();
    float tsr = 0.f, tqr = 0.f, tsi = 0.f, tqi = 0.f;
#pragma unroll
    for (int k = 0; k < 8; k++) {
        tsr += red[0][k][tt]; tqr += red[1][k][tt];
        tsi += red[2][k][tt]; tqi += red[3][k][tt];
    }
    float mr  = tsr * (1.f/DM), mi_ = tsi * (1.f/DM);
    float var_r = tqr * (1.f/DM) - mr*mr;
    float var_i = tqi * (1.f/DM) - mi_*mi_;
    float rr = rsqrtf(var_r + 1e-5f);
    float ri = rsqrtf(var_i + 1e-5f);
#pragma unroll
    for (int j = 0; j < 32; j++) {
        int g = gg*32 + j;
        long off = ((long)b*DM + g)*TLEN + t;
        g_zr[off] = (vr[j] - mr)  * rr * gamma_r[l*DM + g] + beta_r[l*DM + g];
        g_zi[off] = (vi[j] - mi_) * ri * gamma_i[l*DM + g] + beta_i[l*DM + g];
    }
}

// ---------------- launch ------------------------------------------------------
extern "C" void kernel_launch(void* const* d_in, const int* in_sizes, int n_in,
                              void* d_out, int out_size)
{
    const float* x          = (const float*)d_in[0];
    const float* enc_Wr     = (const float*)d_in[1];
    const float* enc_Wi     = (const float*)d_in[2];
    const float* enc_br     = (const float*)d_in[3];
    const float* enc_bi     = (const float*)d_in[4];
    const float* log_dt     = (const float*)d_in[5];
    const float* log_A_real = (const float*)d_in[6];
    const float* A_imag     = (const float*)d_in[7];
    const float* C_r        = (const float*)d_in[8];
    const float* C_i        = (const float*)d_in[9];
    const float* Dvec       = (const float*)d_in[10];
    const float* out_Wr     = (const float*)d_in[11];
    const float* out_Wi     = (const float*)d_in[12];
    const float* out_br     = (const float*)d_in[13];
    const float* out_bi     = (const float*)d_in[14];
    const float* ln_gamma_r = (const float*)d_in[15];
    const float* ln_gamma_i = (const float*)d_in[16];
    const float* ln_beta_r  = (const float*)d_in[17];
    const float* ln_beta_i  = (const float*)d_in[18];
    const float* dec_Wr     = (const float*)d_in[19];
    const float* dec_Wi     = (const float*)d_in[20];
    const float* dec_br     = (const float*)d_in[21];
    const float* dec_bi     = (const float*)d_in[22];

    precompute_kernel<<<(NL*DM*NST + 255)/256, 256>>>(log_dt, log_A_real, A_imag, C_r, C_i);

    long te = (long)512*KTE;
    packA<<<(int)((te + 255)/256), 256>>>(enc_Wr, enc_Wi, DIN, DM, DIN, KPE, 256, 0, te);
    long toAll = (long)NL*512*KTM;
    packA<<<(int)((toAll + 255)/256), 256>>>(out_Wr, out_Wi, DM, DM, DM, KPM, 256, 1, toAll);
    long td = (long)1152*KTM;
    packA<<<(int)((td + 255)/256), 256>>>(dec_Wr, dec_Wi, DM, DIN, DM, KPM, 576, 2, td);

    conv_x<<<dim3(32, KPE/64, BATCH), 128>>>(0, x, KPE, DIN);
    mma_gemm<<<dim3(16, 4, BATCH), 256>>>(0, 0, enc_br, enc_bi, nullptr);   // launch #6 -> ncu

    for (int l = 0; l < NL; l++) {
        scan_kernel<<<(BATCH*DM)/4, 128>>>(l, Dvec);
        conv_x<<<dim3(32, KPM/64, BATCH), 128>>>(1, nullptr, KPM, DM);
        mma_gemm<<<dim3(16, 4, BATCH), 256>>>(1, l, out_br + l*DM, out_bi + l*DM, nullptr);
        ln_kernel<<<dim3(TLEN/32, BATCH), 256>>>(l, ln_gamma_r, ln_gamma_i, ln_beta_r, ln_beta_i);
    }

    conv_x<<<dim3(32, KPM/64, BATCH), 128>>>(2, nullptr, KPM, DM);
    mma_gemm<<<dim3(16, 9, BATCH), 256>>>(2, 0, dec_br, dec_bi, (float*)d_out);
}

// round 16
// speedup vs baseline: 1.4180x; 1.0267x over previous
#include <cuda_runtime.h>
#include <cuda_bf16.h>
#include <cstdint>
#include <math.h>

#define BATCH 8
#define DM    256
#define TLEN  2048
#define DIN   514
#define NL    4
#define NST   32
#define KPE   576
#define KPM   256
#define KTE   (6*KPE)   // logical K' encoder
#define KTM   (6*KPM)   // logical K' mid/decoder

typedef unsigned long long u64;

// ---------------- scratch ----------------
__device__ __align__(16) float g_zr [BATCH*DM*TLEN];
__device__ __align__(16) float g_zi [BATCH*DM*TLEN];
__device__ __align__(16) float g_ygr[BATCH*DM*TLEN];
__device__ __align__(16) float g_ygi[BATCH*DM*TLEN];
__device__ __align__(16) float g_or [BATCH*DM*TLEN];
__device__ __align__(16) float g_oi [BATCH*DM*TLEN];
__device__ float g_ar [NL*DM*NST];
__device__ float g_ai [NL*DM*NST];
__device__ float g_cr [NL*DM*NST];
__device__ float g_ci [NL*DM*NST];
// X' operands, 4 PHYSICAL blocks [RH,RL,IH,IL]: [b][t][4*Kp] bf16
__device__ __align__(16) __nv_bfloat16 g_xe[(long)BATCH*TLEN*4*KPE];
__device__ __align__(16) __nv_bfloat16 g_xm[(long)BATCH*TLEN*4*KPM];
__device__ __align__(16) __nv_bfloat16 g_xd[(long)BATCH*TLEN*4*KPM];
// A operands: [m][K'] bf16 (6 logical blocks), m = [R rows | I rows]
__device__ __align__(16) __nv_bfloat16 g_aenc[512*KTE];
__device__ __align__(16) __nv_bfloat16 g_aout[NL*512*KTM];
__device__ __align__(16) __nv_bfloat16 g_adec[1152*KTM];

// ---------------- helpers ----------------
__device__ __forceinline__ u64 pk(float lo, float hi) {
    u64 r; asm("mov.b64 %0, {%1, %2};" : "=l"(r) : "f"(lo), "f"(hi)); return r;
}
__device__ __forceinline__ float2 upk(u64 v) {
    float2 f; asm("mov.b64 {%0, %1}, %2;" : "=f"(f.x), "=f"(f.y) : "l"(v)); return f;
}
__device__ __forceinline__ u64 fma2v(u64 a, u64 b, u64 c) {
    u64 r; asm("fma.rn.f32x2 %0, %1, %2, %3;" : "=l"(r) : "l"(a), "l"(b), "l"(c)); return r;
}
__device__ __forceinline__ u64 mul2v(u64 a, u64 b) {
    u64 r; asm("mul.rn.f32x2 %0, %1, %2;" : "=l"(r) : "l"(a), "l"(b)); return r;
}
__device__ __forceinline__ u64 add2v(u64 a, u64 b) {
    u64 r; asm("add.rn.f32x2 %0, %1, %2;" : "=l"(r) : "l"(a), "l"(b)); return r;
}
__device__ __forceinline__ void mma16816(float* c, const uint32_t* a, uint32_t b0, uint32_t b1) {
    asm volatile("mma.sync.aligned.m16n8k16.row.col.f32.bf16.bf16.f32 "
                 "{%0,%1,%2,%3}, {%4,%5,%6,%7}, {%8,%9}, {%0,%1,%2,%3};"
                 : "+f"(c[0]), "+f"(c[1]), "+f"(c[2]), "+f"(c[3])
                 : "r"(a[0]), "r"(a[1]), "r"(a[2]), "r"(a[3]), "r"(b0), "r"(b1));
}
__device__ __forceinline__ float gelu_tanh(float x) {
    float x3 = x * x * x;
    float t  = 0.7978845608028654f * fmaf(0.044715f, x3, x);
    float th;
    asm("tanh.approx.f32 %0, %1;" : "=f"(th) : "f"(t));
    return 0.5f * x * (1.0f + th);
}

// ---------------- S4D coefficient precompute ----------------
__global__ void precompute_kernel(const float* __restrict__ log_dt,
                                  const float* __restrict__ log_A_real,
                                  const float* __restrict__ A_imag,
                                  const float* __restrict__ C_r,
                                  const float* __restrict__ C_i)
{
    int idx = blockIdx.x * blockDim.x + threadIdx.x;
    if (idx >= NL*DM*NST) return;
    int h = (idx / NST) % DM;
    int l = idx / (NST*DM);
    double dt  = exp((double)log_dt[l*DM + h]);
    double Are = -exp((double)log_A_real[idx]);
    double Aim = (double)A_imag[idx];
    double er  = exp(Are * dt);
    double arr = er * cos(Aim * dt);
    double aii = er * sin(Aim * dt);
    g_ar[idx] = (float)arr;
    g_ai[idx] = (float)aii;
    double e1r = arr - 1.0, e1i = aii;
    double den = Are*Are + Aim*Aim;
    double qr  = (e1r*Are + e1i*Aim) / den;
    double qi  = (e1i*Are - e1r*Aim) / den;
    double cr  = (double)C_r[idx], ci = (double)C_i[idx];
    g_cr[idx] = (float)(cr*qr - ci*qi);
    g_ci[idx] = (float)(cr*qi + ci*qr);
}

// ---------------- A prepack (validated; 6 logical blocks) ------------------------
__global__ void packA(const float* __restrict__ Wr, const float* __restrict__ Wi,
                      int ld, int Greal, int Kreal, int Kp, int Mr,
                      int which, long total)
{
    long idx = (long)blockIdx.x*blockDim.x + threadIdx.x;
    if (idx >= total) return;
    __nv_bfloat16* dst;
    const float *WrL_, *WiL_;
    long lidx = idx;
    if (which == 1) {
        int layer = (int)(idx / ((long)512*KTM));
        lidx = idx % ((long)512*KTM);
        dst = g_aout + (long)layer*512*KTM;
        WrL_ = Wr + (long)layer*DM*DM;
        WiL_ = Wi + (long)layer*DM*DM;
    } else {
        dst = (which == 0) ? g_aenc : g_adec;
        WrL_ = Wr; WiL_ = Wi;
    }
    int Kt = 6*Kp;
    int m  = (int)(lidx / Kt);
    int kp = (int)(lidx % Kt);
    int bk = kp / Kp, k = kp % Kp;
    int isR = m < Mr;
    int g = isR ? m : m - Mr;
    float w = 0.f;
    if (g < Greal && k < Kreal) {
        const float* W = isR ? (bk < 3 ? WrL_ : WiL_) : (bk < 3 ? WiL_ : WrL_);
        float s = (isR && bk >= 3) ? -1.f : 1.f;
        w = s * W[(long)g*ld + k];
    }
    __nv_bfloat16 h = __float2bfloat16(w);
    if (bk % 3 == 2) h = __float2bfloat16(w - __bfloat162float(h));
    dst[lidx] = h;
}

// ---------------- X convert: 4 physical blocks [RH,RL,IH,IL] ---------------------
__global__ __launch_bounds__(128) void conv_x(int mode, const float* __restrict__ xsrc,
                                              int Kp, int Kreal)
{
    __shared__ float sre[64][65], sim[64][65];
    int tt = blockIdx.x, chunk = blockIdx.y, b = blockIdx.z;
    int Kts = 4*Kp;
    int tid = threadIdx.x;
    __nv_bfloat16* dst = (mode == 0) ? g_xe : (mode == 1) ? g_xm : g_xd;
    for (int idx = tid; idx < 4096; idx += 128) {
        int k = idx >> 6, t = idx & 63;
        int kg = chunk*64 + k, tg = tt*64 + t;
        float re = 0.f, im = 0.f;
        if (kg < Kreal) {
            if (mode == 0) {
                const float* p = xsrc + ((((long)b*DIN + kg)*TLEN + tg) << 1);
                re = p[0]; im = p[1];
            } else {
                long off = ((long)b*DM + kg)*TLEN + tg;
                if (mode == 1) { re = g_ygr[off]; im = g_ygi[off]; }
                else           { re = g_zr[off];  im = g_zi[off];  }
            }
        }
        sre[k][t] = re; sim[k][t] = im;
    }
    __syncthreads();
    for (int idx = tid; idx < 2048; idx += 128) {
        int t = idx >> 5, k2 = (idx & 31)*2;
        float r0 = sre[k2][t],   i0 = sim[k2][t];
        float r1 = sre[k2+1][t], i1 = sim[k2+1][t];
        __nv_bfloat16 rh0 = __float2bfloat16(r0), rh1 = __float2bfloat16(r1);
        __nv_bfloat16 rl0 = __float2bfloat16(r0 - __bfloat162float(rh0));
        __nv_bfloat16 rl1 = __float2bfloat16(r1 - __bfloat162float(rh1));
        __nv_bfloat16 ih0 = __float2bfloat16(i0), ih1 = __float2bfloat16(i1);
        __nv_bfloat16 il0 = __float2bfloat16(i0 - __bfloat162float(ih0));
        __nv_bfloat16 il1 = __float2bfloat16(i1 - __bfloat162float(ih1));
        uint32_t RH = ((uint32_t)*(uint16_t*)&rh1 << 16) | *(uint16_t*)&rh0;
        uint32_t RL = ((uint32_t)*(uint16_t*)&rl1 << 16) | *(uint16_t*)&rl0;
        uint32_t IH = ((uint32_t)*(uint16_t*)&ih1 << 16) | *(uint16_t*)&ih0;
        uint32_t IL = ((uint32_t)*(uint16_t*)&il1 << 16) | *(uint16_t*)&il0;
        long base = ((long)b*TLEN + tt*64 + t)*Kts + chunk*64 + k2;
        *(uint32_t*)(dst + base)        = RH;
        *(uint32_t*)(dst + base + Kp)   = RL;
        *(uint32_t*)(dst + base + 2*Kp) = IH;
        *(uint32_t*)(dst + base + 3*Kp) = IL;
    }
}

// ---------------- register-prefetch + smem-double-buffer MMA GEMM ----------------
// Logical B blocks [RH,RL,RH,IH,IL,IH] -> physical blocks via map {0,1,0,2,3,2}.
__global__ __launch_bounds__(256, 2) void mma_gemm(int which, int layer,
    const float* __restrict__ bR, const float* __restrict__ bI,
    float* __restrict__ dout)
{
    __shared__ __nv_bfloat16 sA[2][128][40];
    __shared__ __nv_bfloat16 sB[2][128][40];
    const __nv_bfloat16 *A, *X;
    int Kt, Kp, Mr;
    if (which == 0)      { A = g_aenc; X = g_xe; Kt = KTE; Kp = KPE; Mr = 256; }
    else if (which == 1) { A = g_aout + (long)layer*512*KTM; X = g_xm; Kt = KTM; Kp = KPM; Mr = 256; }
    else                 { A = g_adec; X = g_xd; Kt = KTM; Kp = KPM; Mr = 576; }
    int Kts = 4*Kp;
    float* outR = (which == 0) ? g_zr : g_or;
    float* outI = (which == 0) ? g_zi : g_oi;

    int tid = threadIdx.x;
    int t0 = blockIdx.x*128, m0 = blockIdx.y*128, b = blockIdx.z;
    int nc = Kt >> 5;
    const __nv_bfloat16* Xb = X + (long)b*TLEN*Kts;
    int wid = tid >> 5, lane = tid & 31;
    int wg = (wid >> 2)*64, wt = (wid & 3)*32;
    int gid = lane >> 2, tig = lane & 3;
    int rowb = tid >> 4, colb = (tid & 15)*2;

    const int bmap[6] = {0, 1, 0, 2, 3, 2};

    float acc[4][4][4];
#pragma unroll
    for (int i = 0; i < 4; i++)
#pragma unroll
        for (int j = 0; j < 4; j++)
#pragma unroll
            for (int r = 0; r < 4; r++) acc[i][j][r] = 0.f;

    const __nv_bfloat16* Abase = A  + ((long)m0 + rowb)*Kt + colb;
    const __nv_bfloat16* Brow  = Xb + ((long)t0 + rowb)*Kts + colb;

    uint32_t ra[8], rb[8];
#pragma unroll
    for (int q = 0; q < 8; q++) ra[q] = *(const uint32_t*)(Abase + (long)q*16*Kt);
    {   // chunk 0: lb=0, kin=0 -> physical offset 0
#pragma unroll
        for (int q = 0; q < 8; q++) rb[q] = *(const uint32_t*)(Brow + (long)q*16*Kts);
    }
    int kin = 0, lb = 0;

    for (int c = 0; c < nc; c++) {
        int buf = c & 1;
#pragma unroll
        for (int q = 0; q < 8; q++) *(uint32_t*)&sA[buf][rowb + q*16][colb] = ra[q];
#pragma unroll
        for (int q = 0; q < 8; q++) *(uint32_t*)&sB[buf][rowb + q*16][colb] = rb[q];
        __syncthreads();
        if (c + 1 < nc) {
            kin += 32;
            if (kin == Kp) { kin = 0; lb++; }
            long pco = (long)bmap[lb]*Kp + kin;
            const __nv_bfloat16* An = Abase + (c+1)*32;
            const __nv_bfloat16* Bn = Brow + pco;
#pragma unroll
            for (int q = 0; q < 8; q++) ra[q] = *(const uint32_t*)(An + (long)q*16*Kt);
#pragma unroll
            for (int q = 0; q < 8; q++) rb[q] = *(const uint32_t*)(Bn + (long)q*16*Kts);
        }
#pragma unroll
        for (int kk = 0; kk < 2; kk++) {
            int cb = kk*16 + tig*2;
            uint32_t af[4][4];
#pragma unroll
            for (int mt = 0; mt < 4; mt++) {
                int r = wg + mt*16 + gid;
                af[mt][0] = *(uint32_t*)&sA[buf][r][cb];
                af[mt][1] = *(uint32_t*)&sA[buf][r+8][cb];
                af[mt][2] = *(uint32_t*)&sA[buf][r][cb+8];
                af[mt][3] = *(uint32_t*)&sA[buf][r+8][cb+8];
            }
            uint32_t bf[4][2];
#pragma unroll
            for (int nt = 0; nt < 4; nt++) {
                int n = wt + nt*8 + gid;
                bf[nt][0] = *(uint32_t*)&sB[buf][n][cb];
                bf[nt][1] = *(uint32_t*)&sB[buf][n][cb+8];
            }
#pragma unroll
            for (int mt = 0; mt < 4; mt++)
#pragma unroll
                for (int nt = 0; nt < 4; nt++)
                    mma16816(acc[mt][nt], af[mt], bf[nt][0], bf[nt][1]);
        }
    }

#pragma unroll
    for (int mt = 0; mt < 4; mt++) {
#pragma unroll
        for (int nt = 0; nt < 4; nt++) {
            int t = t0 + wt + nt*8 + tig*2;
#pragma unroll
            for (int h = 0; h < 2; h++) {
                int mm = m0 + wg + mt*16 + gid + h*8;
                float v0 = acc[mt][nt][h*2], v1 = acc[mt][nt][h*2+1];
                int isR = mm < Mr;
                int g = isR ? mm : mm - Mr;
                if (which == 2) {
                    if (g < DIN) {
                        float bb = isR ? bR[g] : bI[g];
                        float* p = dout + ((((long)b*DIN + g)*TLEN + t) << 1) + (isR ? 0 : 1);
                        p[0] = v0 + bb; p[2] = v1 + bb;
                    }
                } else {
                    float bb = isR ? bR[g] : bI[g];
                    long off = ((long)b*DM + g)*TLEN + t;
                    float2 v = make_float2(v0 + bb, v1 + bb);
                    if (which == 1) {   // fuse residual: o += z
                        float2 z = *(float2*)&(isR ? g_zr : g_zi)[off];
                        v.x += z.x; v.y += z.y;
                    }
                    float* base = isR ? outR : outI;
                    *(float2*)&base[off] = v;
                }
            }
        }
    }
}

// ---------------- per-layer S4D scan (f32x2) + D-skip + gelu ---------------------
__global__ __launch_bounds__(128) void scan_kernel(int layer, const float* __restrict__ Dvec)
{
    __shared__ u64 uS[4][32];
    __shared__ u64 prodS[4][32][33];
    int wid  = threadIdx.x >> 5;
    int lane = threadIdx.x & 31;
    int ch = blockIdx.x * 4 + wid;
    int b  = ch >> 8;
    int h  = ch & 255;
    int pidx = (layer*DM + h)*NST + lane;
    float ar = g_ar[pidx], ai = g_ai[pidx];
    float cr = g_cr[pidx], ci = g_ci[pidx];
    float Dh = Dvec[layer*DM + h];
    u64 Arr = pk(ar, ar), Ani = pk(-ai, ai);
    u64 Crr = pk(cr, cr), Cni = pk(-ci, ci);
    long base = ((long)b*DM + h)*TLEN;
    const float* zr = g_zr + base;
    const float* zi = g_zi + base;
    float* yro = g_ygr + base;
    float* yio = g_ygi + base;

    u64 P = pk(0.f, 0.f), Q = P;
    for (int t0 = 0; t0 < TLEN; t0 += 32) {
        float ur_l = zr[t0 + lane];
        float ui_l = zi[t0 + lane];
        uS[wid][lane] = pk(ur_l, ui_l);
        __syncwarp();
#pragma unroll
        for (int j = 0; j < 32; j++) {
            u64 U = uS[wid][j];
            u64 t1 = fma2v(Arr, P, U);
            P = fma2v(Ani, Q, t1);
            float2 pf = upk(P);
            Q = pk(pf.y, pf.x);
            u64 w = mul2v(Crr, P);
            w = fma2v(Cni, Q, w);
            prodS[wid][j][lane] = w;
        }
        __syncwarp();
        u64 acc = pk(Dh*ur_l, Dh*ui_l);
#pragma unroll
        for (int q = 0; q < 32; q++)
            acc = add2v(acc, prodS[wid][lane][q]);
        float2 y = upk(acc);
        yro[t0 + lane] = gelu_tanh(y.x);
        yio[t0 + lane] = gelu_tanh(y.y);
        __syncwarp();
    }
}

// ---------------- complex LayerNorm over channels (input = z+o in g_o) -----------
__global__ __launch_bounds__(256) void ln_kernel(int l,
    const float* __restrict__ gamma_r, const float* __restrict__ gamma_i,
    const float* __restrict__ beta_r,  const float* __restrict__ beta_i)
{
    int b  = blockIdx.y;
    int t0 = blockIdx.x * 32;
    int tt = threadIdx.x & 31;
    int gg = threadIdx.x >> 5;
    int t  = t0 + tt;

    float vr[32], vi[32];
    float sr = 0.f, qr = 0.f, si = 0.f, qi = 0.f;
#pragma unroll
    for (int j = 0; j < 32; j++) {
        int g = gg*32 + j;
        long off = ((long)b*DM + g)*TLEN + t;
        float r  = g_or[off];
        float i_ = g_oi[off];
        vr[j] = r; vi[j] = i_;
        sr += r;  qr = fmaf(r, r, qr);
        si += i_; qi = fmaf(i_, i_, qi);
    }
    __shared__ float red[4][8][32];
    red[0][gg][tt] = sr; red[1][gg][tt] = qr;
    red[2][gg][tt] = si; red[3][gg][tt] = qi;
    __syncthreads();
    float tsr = 0.f, tqr = 0.f, tsi = 0.f, tqi = 0.f;
#pragma unroll
    for (int k = 0; k < 8; k++) {
        tsr += red[0][k][tt]; tqr += red[1][k][tt];
        tsi += red[2][k][tt]; tqi += red[3][k][tt];
    }
    float mr  = tsr * (1.f/DM), mi_ = tsi * (1.f/DM);
    float var_r = tqr * (1.f/DM) - mr*mr;
    float var_i = tqi * (1.f/DM) - mi_*mi_;
    float rr = rsqrtf(var_r + 1e-5f);
    float ri = rsqrtf(var_i + 1e-5f);
#pragma unroll
    for (int j = 0; j < 32; j++) {
        int g = gg*32 + j;
        long off = ((long)b*DM + g)*TLEN + t;
        g_zr[off] = (vr[j] - mr)  * rr * gamma_r[l*DM + g] + beta_r[l*DM + g];
        g_zi[off] = (vi[j] - mi_) * ri * gamma_i[l*DM + g] + beta_i[l*DM + g];
    }
}

// ---------------- launch ------------------------------------------------------
extern "C" void kernel_launch(void* const* d_in, const int* in_sizes, int n_in,
                              void* d_out, int out_size)
{
    const float* x          = (const float*)d_in[0];
    const float* enc_Wr     = (const float*)d_in[1];
    const float* enc_Wi     = (const float*)d_in[2];
    const float* enc_br     = (const float*)d_in[3];
    const float* enc_bi     = (const float*)d_in[4];
    const float* log_dt     = (const float*)d_in[5];
    const float* log_A_real = (const float*)d_in[6];
    const float* A_imag     = (const float*)d_in[7];
    const float* C_r        = (const float*)d_in[8];
    const float* C_i        = (const float*)d_in[9];
    const float* Dvec       = (const float*)d_in[10];
    const float* out_Wr     = (const float*)d_in[11];
    const float* out_Wi     = (const float*)d_in[12];
    const float* out_br     = (const float*)d_in[13];
    const float* out_bi     = (const float*)d_in[14];
    const float* ln_gamma_r = (const float*)d_in[15];
    const float* ln_gamma_i = (const float*)d_in[16];
    const float* ln_beta_r  = (const float*)d_in[17];
    const float* ln_beta_i  = (const float*)d_in[18];
    const float* dec_Wr     = (const float*)d_in[19];
    const float* dec_Wi     = (const float*)d_in[20];
    const float* dec_br     = (const float*)d_in[21];
    const float* dec_bi     = (const float*)d_in[22];

    precompute_kernel<<<(NL*DM*NST + 255)/256, 256>>>(log_dt, log_A_real, A_imag, C_r, C_i);

    long te = (long)512*KTE;
    packA<<<(int)((te + 255)/256), 256>>>(enc_Wr, enc_Wi, DIN, DM, DIN, KPE, 256, 0, te);
    long toAll = (long)NL*512*KTM;
    packA<<<(int)((toAll + 255)/256), 256>>>(out_Wr, out_Wi, DM, DM, DM, KPM, 256, 1, toAll);
    long td = (long)1152*KTM;
    packA<<<(int)((td + 255)/256), 256>>>(dec_Wr, dec_Wi, DM, DIN, DM, KPM, 576, 2, td);

    conv_x<<<dim3(32, KPE/64, BATCH), 128>>>(0, x, KPE, DIN);
    mma_gemm<<<dim3(16, 4, BATCH), 256>>>(0, 0, enc_br, enc_bi, nullptr);

    for (int l = 0; l < NL; l++) {
        scan_kernel<<<(BATCH*DM)/4, 128>>>(l, Dvec);
        conv_x<<<dim3(32, KPM/64, BATCH), 128>>>(1, nullptr, KPM, DM);
        mma_gemm<<<dim3(16, 4, BATCH), 256>>>(1, l, out_br + l*DM, out_bi + l*DM, nullptr);
        ln_kernel<<<dim3(TLEN/32, BATCH), 256>>>(l, ln_gamma_r, ln_gamma_i, ln_beta_r, ln_beta_i);
    }

    conv_x<<<dim3(32, KPM/64, BATCH), 128>>>(2, nullptr, KPM, DM);
    mma_gemm<<<dim3(16, 9, BATCH), 256>>>(2, 0, dec_br, dec_bi, (float*)d_out);
}